// round 11
// baseline (speedup 1.0000x reference)
#include <cuda_runtime.h>
#include <stdint.h>

// out[k,l] = sum_j mitchell_mul(x[k,j], weight[l,j]) + bias[l]
// Mitchell approx multiply == integer add of offset float bit patterns:
//   packed(v) = (sign<<31) | max(bits(|v|) - 0x1FC00000, 0)
//   mitchell(a,b) = reinterpret_float(packed(a) + packed(b))
// (low fields < 2^30 for these inputs -> no carry into the sign bit; signs XOR)
//
// R11 == R9/R10 resubmitted (two broker-level container failures; same error
// signature previously seen on an empty stub, so content-independent):
// single-kernel direct full-K GEMM. 128 uniform CTAs (1/SM, one wave),
// 64x32 CTA tile, 4x2 thread tile, K=1024 in 32 double-buffered BK=32 stages,
// bias fused in the epilogue. No split-K partials, no reduce kernel.

#define NROWS 512
#define MROWS 512
#define KDIM  1024
#define BK 32
#define BM 64                // x rows per CTA
#define BN 32                // w rows per CTA
#define PADM (BM + 4)        // 68 words: 272B rows, 16B-aligned (LDS.128 ok)
#define PADN (BN + 2)        // 34 words: 136B rows, 8B-aligned (LDS.64 ok)
#define TM 4
#define TN 2
#define NSTAGE (KDIM / BK)   // 32

__device__ __forceinline__ unsigned int pack1(unsigned int b) {
    unsigned int mag = b & 0x7FFFFFFFu;
    unsigned int low = (mag > 0x1FC00000u) ? (mag - 0x1FC00000u) : 0u;
    return (b & 0x80000000u) | low;
}

__global__ __launch_bounds__(256, 1) void mitchell_mm_kernel(
    const uint4* __restrict__ xq, const uint4* __restrict__ wq,
    const float* __restrict__ bias, float* __restrict__ out) {
    __shared__ unsigned int Xs[2][BK][PADM];   // [buf][k][row]
    __shared__ unsigned int Ws[2][BK][PADN];

    const int tid = threadIdx.x;            // 256 threads: 16 x 16
    const int tx = tid & 15;                // col group (TN=2)
    const int ty = tid >> 4;                // row group (TM=4)
    const int rowBase = blockIdx.y * BM;
    const int colBase = blockIdx.x * BN;
    const int K4 = KDIM / 4;

    float acc[TM][TN];
#pragma unroll
    for (int i = 0; i < TM; i++)
#pragma unroll
        for (int j = 0; j < TN; j++) acc[i][j] = 0.0f;

    // Staging per stage: X 64x32 = 512 uint4 (2/thread), W 32x32 = 256 uint4 (1/thread).
    const int xrow = tid >> 2;              // 0..63
    const int xkq  = tid & 3;               // x k-quad 0..3 (plus +4 for 2nd vec)
    const int wrow = tid >> 3;              // 0..31
    const int wkq  = tid & 7;               // w k-quad 0..7

    uint4 px[2], pw;
    auto gload = [&](int kk) {
        int g = kk / 4;
        const uint4* xr = xq + (rowBase + xrow) * K4 + g;
        px[0] = xr[xkq];
        px[1] = xr[xkq + 4];
        pw = wq[(colBase + wrow) * K4 + g + wkq];
    };

    auto sstore = [&](int b) {
        Xs[b][xkq * 4 + 0][xrow] = pack1(px[0].x);
        Xs[b][xkq * 4 + 1][xrow] = pack1(px[0].y);
        Xs[b][xkq * 4 + 2][xrow] = pack1(px[0].z);
        Xs[b][xkq * 4 + 3][xrow] = pack1(px[0].w);
        Xs[b][(xkq + 4) * 4 + 0][xrow] = pack1(px[1].x);
        Xs[b][(xkq + 4) * 4 + 1][xrow] = pack1(px[1].y);
        Xs[b][(xkq + 4) * 4 + 2][xrow] = pack1(px[1].z);
        Xs[b][(xkq + 4) * 4 + 3][xrow] = pack1(px[1].w);
        Ws[b][wkq * 4 + 0][wrow] = pack1(pw.x);
        Ws[b][wkq * 4 + 1][wrow] = pack1(pw.y);
        Ws[b][wkq * 4 + 2][wrow] = pack1(pw.z);
        Ws[b][wkq * 4 + 3][wrow] = pack1(pw.w);
    };

    gload(0);
    sstore(0);
    __syncthreads();

#pragma unroll 1
    for (int s = 0; s < NSTAGE; s++) {
        const int buf = s & 1;
        if (s + 1 < NSTAGE) gload((s + 1) * BK);   // LDG latency under this stage

        // 2-deep register pipeline over k: load k+1 before computing k.
        unsigned int ap[2][TM], bp[2][TN];
        {
            uint4 a0 = *reinterpret_cast<const uint4*>(&Xs[buf][0][ty * TM]);
            uint2 b0 = *reinterpret_cast<const uint2*>(&Ws[buf][0][tx * TN]);
            ap[0][0] = a0.x; ap[0][1] = a0.y; ap[0][2] = a0.z; ap[0][3] = a0.w;
            bp[0][0] = b0.x; bp[0][1] = b0.y;
        }
#pragma unroll
        for (int k = 0; k < BK; k++) {
            const int cur = k & 1, nxt = cur ^ 1;
            if (k + 1 < BK) {
                uint4 a0 = *reinterpret_cast<const uint4*>(&Xs[buf][k + 1][ty * TM]);
                uint2 b0 = *reinterpret_cast<const uint2*>(&Ws[buf][k + 1][tx * TN]);
                ap[nxt][0] = a0.x; ap[nxt][1] = a0.y; ap[nxt][2] = a0.z; ap[nxt][3] = a0.w;
                bp[nxt][0] = b0.x; bp[nxt][1] = b0.y;
            }
#pragma unroll
            for (int i = 0; i < TM; i++)
#pragma unroll
                for (int j = 0; j < TN; j++)
                    acc[i][j] += __uint_as_float(ap[cur][i] + bp[cur][j]);
        }

        if (s + 1 < NSTAGE) sstore(buf ^ 1);   // other buffer; readers bar'd already
        __syncthreads();
    }

    // Epilogue: add bias, write final output directly.
    float2 bv = *reinterpret_cast<const float2*>(&bias[colBase + tx * TN]);
#pragma unroll
    for (int i = 0; i < TM; i++) {
        int r = rowBase + ty * TM + i;
        float2 o;
        o.x = acc[i][0] + bv.x;
        o.y = acc[i][1] + bv.y;
        *reinterpret_cast<float2*>(&out[r * MROWS + colBase + tx * TN]) = o;
    }
}

extern "C" void kernel_launch(void* const* d_in, const int* in_sizes, int n_in,
                              void* d_out, int out_size) {
    const float* x    = (const float*)d_in[0];
    const float* w    = (const float*)d_in[1];
    const float* bias = (const float*)d_in[2];
    float* out = (float*)d_out;

    dim3 grid(MROWS / BN, NROWS / BM);   // (16,8) = 128 CTAs, 1/SM, one wave
    mitchell_mm_kernel<<<grid, 256>>>((const uint4*)x, (const uint4*)w, bias, out);
}

// round 12
// speedup vs baseline: 1.0563x; 1.0563x over previous
#include <cuda_runtime.h>
#include <stdint.h>

// out[k,l] = sum_j mitchell_mul(x[k,j], weight[l,j]) + bias[l]
// Mitchell approx multiply == integer add of offset float bit patterns:
//   packed(v) = (sign<<31) | max(bits(|v|) - 0x1FC00000, 0)
//   mitchell(a,b) = reinterpret_float(packed(a) + packed(b))
// (low fields < 2^30 for these inputs -> no carry into the sign bit; signs XOR)
//
// R12: occupancy + balance + fused reduction.
//  - 1024 CTAs of 128 threads (64x32 tile, split-K=8): 8 CTAs/SM resident,
//    ~7 warps/SMSP, 98.9% CTA balance (vs 86.5% for 256/512-CTA grids).
//  - out prefilled with bias; mm CTAs atomicAdd (REDG, no-return) their tiles
//    directly -> no reduce kernel, no 16 MB partials round-trip.

#define NROWS 512
#define MROWS 512
#define KDIM  1024
#define SPLITS 8
#define KC (KDIM / SPLITS)   // 128 k per split
#define BK 16
#define BM 64                // x rows per CTA
#define BN 32                // w rows per CTA
#define PADM (BM + 4)        // 68 words: 272B row stride, 16B-aligned
#define PADN (BN + 4)        // 36 words: 144B row stride, 16B-aligned
#define TM 4
#define TN 4
#define NSTAGE (KC / BK)     // 8

__device__ __forceinline__ unsigned int pack1(unsigned int b) {
    unsigned int mag = b & 0x7FFFFFFFu;
    unsigned int low = (mag > 0x1FC00000u) ? (mag - 0x1FC00000u) : 0u;
    return (b & 0x80000000u) | low;
}

__global__ __launch_bounds__(256) void prefill_kernel(
    const float* __restrict__ bias, float* __restrict__ out) {
    int i4 = blockIdx.x * blockDim.x + threadIdx.x;   // 0..65535 float4s
    reinterpret_cast<float4*>(out)[i4] =
        reinterpret_cast<const float4*>(bias)[i4 & (MROWS / 4 - 1)];
}

__global__ __launch_bounds__(128, 8) void mitchell_mm_kernel(
    const uint4* __restrict__ xq, const uint4* __restrict__ wq,
    float* __restrict__ out) {
    __shared__ unsigned int Xs[2][BK][PADM];   // [buf][k][row]  8704B
    __shared__ unsigned int Ws[2][BK][PADN];   //                4608B

    const int tid = threadIdx.x;            // 128 threads: 8 x 16
    const int tx = tid & 7;                 // col group (TN=4): 8 x 4 = 32 cols
    const int ty = tid >> 3;                // row group (TM=4): 16 x 4 = 64 rows
    const int rowBase = blockIdx.y * BM;
    const int colBase = blockIdx.x * BN;
    const int kBase   = blockIdx.z * KC;
    const int K4 = KDIM / 4;

    float acc[TM][TN];
#pragma unroll
    for (int i = 0; i < TM; i++)
#pragma unroll
        for (int j = 0; j < TN; j++) acc[i][j] = 0.0f;

    // Staging per stage: X 64x16 = 256 uint4 (2/thread), W 32x16 = 128 (1/thread).
    const int srow = tid >> 2;              // 0..31
    const int kq   = tid & 3;               // k-quad 0..3

    uint4 px0, px1, pw;
    auto gload = [&](int kk) {
        int g = (kBase + kk) / 4 + kq;
        px0 = xq[(rowBase + srow) * K4 + g];
        px1 = xq[(rowBase + srow + 32) * K4 + g];
        pw  = wq[(colBase + srow) * K4 + g];
    };

    auto sstore = [&](int b) {
        Xs[b][kq * 4 + 0][srow] = pack1(px0.x);
        Xs[b][kq * 4 + 1][srow] = pack1(px0.y);
        Xs[b][kq * 4 + 2][srow] = pack1(px0.z);
        Xs[b][kq * 4 + 3][srow] = pack1(px0.w);
        Xs[b][kq * 4 + 0][srow + 32] = pack1(px1.x);
        Xs[b][kq * 4 + 1][srow + 32] = pack1(px1.y);
        Xs[b][kq * 4 + 2][srow + 32] = pack1(px1.z);
        Xs[b][kq * 4 + 3][srow + 32] = pack1(px1.w);
        Ws[b][kq * 4 + 0][srow] = pack1(pw.x);
        Ws[b][kq * 4 + 1][srow] = pack1(pw.y);
        Ws[b][kq * 4 + 2][srow] = pack1(pw.z);
        Ws[b][kq * 4 + 3][srow] = pack1(pw.w);
    };

    gload(0);
    sstore(0);
    __syncthreads();

#pragma unroll 1
    for (int s = 0; s < NSTAGE; s++) {
        const int buf = s & 1;
        if (s + 1 < NSTAGE) gload((s + 1) * BK);   // LDG latency under compute

#pragma unroll
        for (int k = 0; k < BK; k++) {
            uint4 a0 = *reinterpret_cast<const uint4*>(&Xs[buf][k][ty * TM]);
            uint4 b0 = *reinterpret_cast<const uint4*>(&Ws[buf][k][tx * TN]);
            unsigned int a[TM] = {a0.x, a0.y, a0.z, a0.w};
            unsigned int b[TN] = {b0.x, b0.y, b0.z, b0.w};
#pragma unroll
            for (int i = 0; i < TM; i++)
#pragma unroll
                for (int j = 0; j < TN; j++)
                    acc[i][j] += __uint_as_float(a[i] + b[j]);
        }

        if (s + 1 < NSTAGE) sstore(buf ^ 1);   // readers of buf^1 bar'd last stage
        __syncthreads();
    }

    // Fused reduction: fire-and-forget float atomics into the bias-prefilled out.
#pragma unroll
    for (int i = 0; i < TM; i++) {
        int r = rowBase + ty * TM + i;
#pragma unroll
        for (int j = 0; j < TN; j++)
            atomicAdd(&out[r * MROWS + colBase + tx * TN + j], acc[i][j]);
    }
}

extern "C" void kernel_launch(void* const* d_in, const int* in_sizes, int n_in,
                              void* d_out, int out_size) {
    const float* x    = (const float*)d_in[0];
    const float* w    = (const float*)d_in[1];
    const float* bias = (const float*)d_in[2];
    float* out = (float*)d_out;

    prefill_kernel<<<NROWS * MROWS / 4 / 256, 256>>>(bias, out);

    dim3 grid(MROWS / BN, NROWS / BM, SPLITS);   // (16,8,8) = 1024 CTAs, 8/SM
    mitchell_mm_kernel<<<grid, 128>>>((const uint4*)x, (const uint4*)w, out);
}

// round 13
// speedup vs baseline: 1.1332x; 1.0728x over previous
#include <cuda_runtime.h>
#include <stdint.h>

// out[k,l] = sum_j mitchell_mul(x[k,j], weight[l,j]) + bias[l]
// Mitchell approx multiply == integer add of offset float bit patterns:
//   packed(v) = (sign<<31) | max(bits(|v|) - 0x1FC00000, 0)
//   mitchell(a,b) = reinterpret_float(packed(a) + packed(b))
// (low fields < 2^30 for these inputs -> no carry into the sign bit; signs XOR)
//
// R13: the measured-best R8 mainloop (256 CTAs, BM128/BN64, TM8/TN4, BK=16
// double-buffered, 2-deep LDS pipeline) with the split-K reduction fused:
// out is prefilled with bias, and each CTA atomicAdds (vector REDG.128,
// fire-and-forget) its 8 float4 rows directly. No partials, no reduce kernel.

#define NROWS 512
#define MROWS 512
#define KDIM  1024
#define SPLITS 8
#define KC (KDIM / SPLITS)   // 128 k per split
#define BK 16
#define BM 128               // x rows per CTA
#define BN 64                // w rows per CTA
#define PADM (BM + 4)
#define PADN (BN + 4)
#define TM 8
#define TN 4
#define NSTAGE (KC / BK)     // 8

__device__ __forceinline__ unsigned int pack1(unsigned int b) {
    unsigned int mag = b & 0x7FFFFFFFu;
    unsigned int low = (mag > 0x1FC00000u) ? (mag - 0x1FC00000u) : 0u;
    return (b & 0x80000000u) | low;
}

__global__ __launch_bounds__(256) void prefill_kernel(
    const float* __restrict__ bias, float* __restrict__ out) {
    int i4 = blockIdx.x * blockDim.x + threadIdx.x;   // 0..65535 float4s
    reinterpret_cast<float4*>(out)[i4] =
        reinterpret_cast<const float4*>(bias)[i4 & (MROWS / 4 - 1)];
}

__global__ __launch_bounds__(256, 2) void mitchell_mm_kernel(
    const uint4* __restrict__ xq, const uint4* __restrict__ wq,
    float* __restrict__ out) {
    __shared__ unsigned int Xs[2][BK][PADM];   // double-buffered [k][row]
    __shared__ unsigned int Ws[2][BK][PADN];

    const int tid = threadIdx.x;            // 256 threads: 16 x 16
    const int tx = tid & 15;                // col group (TN=4)
    const int ty = tid >> 4;                // row group (TM=8)
    const int rowBase = blockIdx.y * BM;
    const int colBase = blockIdx.x * BN;
    const int kBase   = blockIdx.z * KC;
    const int K4 = KDIM / 4;

    float acc[TM][TN];
#pragma unroll
    for (int i = 0; i < TM; i++)
#pragma unroll
        for (int j = 0; j < TN; j++) acc[i][j] = 0.0f;

    // Staging (BK=16): X tile 128x16 = 512 uint4 (2/thread),
    //                  W tile  64x16 = 256 uint4 (1/thread).
    const int xrow = tid >> 2;              // 0..63 (+64 for v=1)
    const int kq   = tid & 3;               // k-quad 0..3

    uint4 px[2], pw;
    auto gload = [&](int kk) {
        int gk4 = (kBase + kk) / 4 + kq;
#pragma unroll
        for (int v = 0; v < 2; v++)
            px[v] = xq[(rowBase + xrow + 64 * v) * K4 + gk4];
        pw = wq[(colBase + xrow) * K4 + gk4];
    };

    auto sstore = [&](int b) {
#pragma unroll
        for (int v = 0; v < 2; v++) {
            int r = xrow + 64 * v;
            Xs[b][kq * 4 + 0][r] = pack1(px[v].x);
            Xs[b][kq * 4 + 1][r] = pack1(px[v].y);
            Xs[b][kq * 4 + 2][r] = pack1(px[v].z);
            Xs[b][kq * 4 + 3][r] = pack1(px[v].w);
        }
        Ws[b][kq * 4 + 0][xrow] = pack1(pw.x);
        Ws[b][kq * 4 + 1][xrow] = pack1(pw.y);
        Ws[b][kq * 4 + 2][xrow] = pack1(pw.z);
        Ws[b][kq * 4 + 3][xrow] = pack1(pw.w);
    };

    gload(0);
    sstore(0);
    __syncthreads();

#pragma unroll 1
    for (int s = 0; s < NSTAGE; s++) {
        const int buf = s & 1;
        if (s + 1 < NSTAGE) gload((s + 1) * BK);   // LDG latency under compute

        // 2-deep register pipeline over k: load k+1 before computing k.
        unsigned int ap[2][TM], bp[2][TN];
        {
            uint4 a0 = *reinterpret_cast<const uint4*>(&Xs[buf][0][ty * TM]);
            uint4 a1 = *reinterpret_cast<const uint4*>(&Xs[buf][0][ty * TM + 4]);
            uint4 b0 = *reinterpret_cast<const uint4*>(&Ws[buf][0][tx * TN]);
            ap[0][0] = a0.x; ap[0][1] = a0.y; ap[0][2] = a0.z; ap[0][3] = a0.w;
            ap[0][4] = a1.x; ap[0][5] = a1.y; ap[0][6] = a1.z; ap[0][7] = a1.w;
            bp[0][0] = b0.x; bp[0][1] = b0.y; bp[0][2] = b0.z; bp[0][3] = b0.w;
        }
#pragma unroll
        for (int k = 0; k < BK; k++) {
            const int cur = k & 1, nxt = cur ^ 1;
            if (k + 1 < BK) {
                uint4 a0 = *reinterpret_cast<const uint4*>(&Xs[buf][k + 1][ty * TM]);
                uint4 a1 = *reinterpret_cast<const uint4*>(&Xs[buf][k + 1][ty * TM + 4]);
                uint4 b0 = *reinterpret_cast<const uint4*>(&Ws[buf][k + 1][tx * TN]);
                ap[nxt][0] = a0.x; ap[nxt][1] = a0.y; ap[nxt][2] = a0.z; ap[nxt][3] = a0.w;
                ap[nxt][4] = a1.x; ap[nxt][5] = a1.y; ap[nxt][6] = a1.z; ap[nxt][7] = a1.w;
                bp[nxt][0] = b0.x; bp[nxt][1] = b0.y; bp[nxt][2] = b0.z; bp[nxt][3] = b0.w;
            }
#pragma unroll
            for (int i = 0; i < TM; i++)
#pragma unroll
                for (int j = 0; j < TN; j++)
                    acc[i][j] += __uint_as_float(ap[cur][i] + bp[cur][j]);
        }

        if (s + 1 < NSTAGE) sstore(buf ^ 1);   // fill other buffer (bar'd last stage)
        __syncthreads();
    }

    // Fused split-K reduction: vector float4 atomics (REDG.128, fire-and-forget)
    // into the bias-prefilled output. TN=4 contiguous cols == one float4.
#pragma unroll
    for (int i = 0; i < TM; i++) {
        int r = rowBase + ty * TM + i;
        atomicAdd(reinterpret_cast<float4*>(&out[r * MROWS + colBase + tx * TN]),
                  make_float4(acc[i][0], acc[i][1], acc[i][2], acc[i][3]));
    }
}

extern "C" void kernel_launch(void* const* d_in, const int* in_sizes, int n_in,
                              void* d_out, int out_size) {
    const float* x    = (const float*)d_in[0];
    const float* w    = (const float*)d_in[1];
    const float* bias = (const float*)d_in[2];
    float* out = (float*)d_out;

    prefill_kernel<<<NROWS * MROWS / 4 / 256, 256>>>(bias, out);

    dim3 grid(MROWS / BN, NROWS / BM, SPLITS);   // (8,4,8) = 256 CTAs, 2/SM
    mitchell_mm_kernel<<<grid, 256>>>((const uint4*)x, (const uint4*)w, out);
}